// round 12
// baseline (speedup 1.0000x reference)
#include <cuda_runtime.h>

// Problem constants
#define DIMC 192
#define RR   48            // DIM/RED
#define BB   4
#define HH   256
#define WW   256
#define PLANE (HH*WW)      // 65536
#define NPLANES (BB*DIMC)  // 768
#define EPS_BN 1e-5f
#define POOL_BLOCKS (NPLANES * 4)

// Scratch (no allocations allowed)
__device__ float g_partial[NPLANES * 4];   // per-quarter-plane sums
__device__ float g_t[BB * RR];             // post-BN-ReLU hidden
__device__ unsigned int g_count;           // zero-initialized; self-resetting

// ---------------------------------------------------------------------------
// Kernel 1: partial sums for channel-wise mean (proven 32.3us body), with:
//  (a) REVERSED plane order (767 -> 0) so the L2 residue at pool-exit covers
//      the planes the conv reads FIRST (conv stays forward / byte-identical),
//  (b) last-block tail computes t = relu(BN(pooled @ w1^T)) [192 values],
//      eliminating any separate middle kernel. Counter self-resets.
// ---------------------------------------------------------------------------
__global__ void __launch_bounds__(256)
pool_partial_kernel(const float* __restrict__ x,
                    const float* __restrict__ w1,
                    const float* __restrict__ gamma,
                    const float* __restrict__ beta,
                    const float* __restrict__ rmean,
                    const float* __restrict__ rvar) {
    int bid = blockIdx.x;                       // [0, 3072)
    int plane = (NPLANES - 1) - (bid >> 2);     // reversed
    int quarter = bid & 3;
    const float4* p = reinterpret_cast<const float4*>(
        x + (size_t)plane * PLANE + quarter * (PLANE / 4));
    float s0 = 0.f, s1 = 0.f, s2 = 0.f, s3 = 0.f;
    #pragma unroll
    for (int j = 0; j < 4; ++j) {
        float4 v0 = p[threadIdx.x + (4*j+0) * 256];
        float4 v1 = p[threadIdx.x + (4*j+1) * 256];
        float4 v2 = p[threadIdx.x + (4*j+2) * 256];
        float4 v3 = p[threadIdx.x + (4*j+3) * 256];
        s0 += (v0.x + v0.y) + (v0.z + v0.w);
        s1 += (v1.x + v1.y) + (v1.z + v1.w);
        s2 += (v2.x + v2.y) + (v2.z + v2.w);
        s3 += (v3.x + v3.y) + (v3.z + v3.w);
    }
    float s = (s0 + s1) + (s2 + s3);
    #pragma unroll
    for (int o = 16; o > 0; o >>= 1) s += __shfl_down_sync(0xffffffffu, s, o);
    __shared__ float sm[8];
    int lane = threadIdx.x & 31, w = threadIdx.x >> 5;
    if (lane == 0) sm[w] = s;
    __syncthreads();
    if (threadIdx.x < 8) {
        float v = sm[threadIdx.x];
        #pragma unroll
        for (int o = 4; o > 0; o >>= 1) v += __shfl_down_sync(0xffu, v, o);
        if (threadIdx.x == 0) g_partial[plane * 4 + quarter] = v;
    }

    // ---- last-block tail: compute t (192 values) ----
    __shared__ int is_last;
    if (threadIdx.x == 0) {
        __threadfence();
        unsigned int v = atomicAdd(&g_count, 1u);
        is_last = (v == POOL_BLOCKS - 1) ? 1 : 0;
    }
    __syncthreads();
    if (!is_last) return;
    __threadfence();

    __shared__ float sp[NPLANES];
    for (int j = threadIdx.x; j < NPLANES; j += 256) {
        sp[j] = (g_partial[4*j] + g_partial[4*j+1] + g_partial[4*j+2] + g_partial[4*j+3])
                * (1.f / (float)PLANE);
    }
    __syncthreads();
    if (threadIdx.x < BB * RR) {
        int b = threadIdx.x / RR;
        int r = threadIdx.x % RR;
        const float* pb = &sp[b * DIMC];
        const float* wr = &w1[r * DIMC];
        float acc = 0.f;
        #pragma unroll 4
        for (int k = 0; k < DIMC; ++k) acc = fmaf(pb[k], wr[k], acc);
        acc = gamma[r] * (acc - rmean[r]) * rsqrtf(rvar[r] + EPS_BN) + beta[r];
        g_t[threadIdx.x] = fmaxf(acc, 0.f);
    }
    if (threadIdx.x == 0) g_count = 0;   // reset for next graph replay
}

// ---------------------------------------------------------------------------
// Kernel 2: fused taps + masked depthwise conv. Grid = 768 planes x 8 chunks
// = 6144 blocks (41.5/SM -> full occupancy, fine balance). Prologue: warps
// 0..3 compute this plane's 4 surviving taps from g_t (192B) and 4 w2 rows.
// Main loop: 8 row-groups of the byte-identical R4/R10 conv body.
// out[y][x] = w0*X[y-1][x-1] + w1*X[y-1][x] + w2*X[y-1][x+1] + w3*X[y][x-1]+b
// ---------------------------------------------------------------------------
__global__ void __launch_bounds__(256, 8)
conv_kernel(const float* __restrict__ x,
            const float* __restrict__ w2,
            const float* __restrict__ b2,
            const float* __restrict__ bias,
            float* __restrict__ out) {
    int plane = blockIdx.x >> 3;       // forward order (proven access pattern)
    int chunk = blockIdx.x & 7;
    int b = plane / DIMC;
    int c = plane % DIMC;
    int lane = threadIdx.x & 31;
    int warp = threadIdx.x >> 5;

    __shared__ float sw[4];
    if (warp < 4) {
        int row = c * 9 + warp;                    // surviving mask-A taps 0..3
        const float* wr = w2 + (size_t)row * RR;
        const float* tb = g_t + b * RR;
        float acc = tb[lane] * wr[lane];
        if (lane < 16) acc = fmaf(tb[lane + 32], wr[lane + 32], acc);
        #pragma unroll
        for (int o = 16; o > 0; o >>= 1)
            acc += __shfl_down_sync(0xffffffffu, acc, o);
        if (lane == 0) sw[warp] = acc + b2[row];
    }
    __syncthreads();

    const float w0 = sw[0], w1v = sw[1], w2v = sw[2], w3 = sw[3];
    const float bv = __ldg(&bias[c]);

    int ty = threadIdx.x >> 6;         // 0..3
    int tx = threadIdx.x & 63;
    int x0 = tx << 2;
    const float* Xp = x   + (size_t)plane * PLANE;
    float*       Op = out + (size_t)plane * PLANE;

    #pragma unroll 2
    for (int rg = 0; rg < 8; ++rg) {
        int y = chunk * 32 + rg * 4 + ty;
        const float* cur = Xp + y * WW;

        float4 c4 = *reinterpret_cast<const float4*>(cur + x0);
        float cl  = (x0 > 0) ? cur[x0 - 1] : 0.f;

        float4 a4 = make_float4(0.f, 0.f, 0.f, 0.f);
        float al = 0.f, ar = 0.f;
        if (y > 0) {
            const float* ab = cur - WW;
            a4 = *reinterpret_cast<const float4*>(ab + x0);
            al = (x0 > 0)      ? ab[x0 - 1] : 0.f;
            ar = (x0 < WW - 4) ? ab[x0 + 4] : 0.f;
        }

        float4 o;
        o.x = fmaf(w0, al,   fmaf(w1v, a4.x, fmaf(w2v, a4.y, fmaf(w3, cl,   bv))));
        o.y = fmaf(w0, a4.x, fmaf(w1v, a4.y, fmaf(w2v, a4.z, fmaf(w3, c4.x, bv))));
        o.z = fmaf(w0, a4.y, fmaf(w1v, a4.z, fmaf(w2v, a4.w, fmaf(w3, c4.y, bv))));
        o.w = fmaf(w0, a4.z, fmaf(w1v, a4.w, fmaf(w2v, ar,   fmaf(w3, c4.z, bv))));

        *reinterpret_cast<float4*>(Op + y * WW + x0) = o;
    }
}

// ---------------------------------------------------------------------------
extern "C" void kernel_launch(void* const* d_in, const int* in_sizes, int n_in,
                              void* d_out, int out_size) {
    const float* x     = (const float*)d_in[0];
    const float* w1    = (const float*)d_in[1];
    const float* gamma = (const float*)d_in[2];
    const float* beta  = (const float*)d_in[3];
    const float* rmean = (const float*)d_in[4];
    const float* rvar  = (const float*)d_in[5];
    const float* w2    = (const float*)d_in[6];
    const float* b2    = (const float*)d_in[7];
    const float* bias  = (const float*)d_in[8];
    float* out = (float*)d_out;

    pool_partial_kernel<<<POOL_BLOCKS, 256>>>(x, w1, gamma, beta, rmean, rvar);
    conv_kernel<<<NPLANES * 8, 256>>>(x, w2, b2, bias, out);
}

// round 13
// speedup vs baseline: 1.2196x; 1.2196x over previous
#include <cuda_runtime.h>

// Problem constants
#define DIMC 192
#define RR   48            // DIM/RED
#define BB   4
#define HH   256
#define WW   256
#define PLANE (HH*WW)      // 65536
#define NPLANES (BB*DIMC)  // 768
#define EPS_BN 1e-5f

// Scratch (no allocations allowed)
__device__ float g_partial[NPLANES * 4];   // per-quarter-plane sums
__device__ float g_t[BB * RR];             // post-BN-ReLU hidden

// ---------------------------------------------------------------------------
// Kernel 1: partial sums for channel-wise mean. Proven 32.3us body, plane
// order REVERSED (767 -> 0) so L2 residue at exit covers the planes the conv
// reads first. No tail, no fences.
// ---------------------------------------------------------------------------
__global__ void __launch_bounds__(256)
pool_partial_kernel(const float* __restrict__ x) {
    int bid = blockIdx.x;                       // [0, 3072)
    int plane = (NPLANES - 1) - (bid >> 2);     // reversed
    int quarter = bid & 3;
    const float4* p = reinterpret_cast<const float4*>(
        x + (size_t)plane * PLANE + quarter * (PLANE / 4));
    float s0 = 0.f, s1 = 0.f, s2 = 0.f, s3 = 0.f;
    #pragma unroll
    for (int j = 0; j < 4; ++j) {
        float4 v0 = p[threadIdx.x + (4*j+0) * 256];
        float4 v1 = p[threadIdx.x + (4*j+1) * 256];
        float4 v2 = p[threadIdx.x + (4*j+2) * 256];
        float4 v3 = p[threadIdx.x + (4*j+3) * 256];
        s0 += (v0.x + v0.y) + (v0.z + v0.w);
        s1 += (v1.x + v1.y) + (v1.z + v1.w);
        s2 += (v2.x + v2.y) + (v2.z + v2.w);
        s3 += (v3.x + v3.y) + (v3.z + v3.w);
    }
    float s = (s0 + s1) + (s2 + s3);
    #pragma unroll
    for (int o = 16; o > 0; o >>= 1) s += __shfl_down_sync(0xffffffffu, s, o);
    __shared__ float sm[8];
    int lane = threadIdx.x & 31, w = threadIdx.x >> 5;
    if (lane == 0) sm[w] = s;
    __syncthreads();
    if (threadIdx.x < 8) {
        float v = sm[threadIdx.x];
        #pragma unroll
        for (int o = 4; o > 0; o >>= 1) v += __shfl_down_sync(0xffu, v, o);
        if (threadIdx.x == 0) g_partial[plane * 4 + quarter] = v;
    }
}

// ---------------------------------------------------------------------------
// Kernel 2: t = relu(BN(pooled @ w1^T)), one WARP per output value.
// 192 outputs = 24 blocks x 8 warps. Each warp: coalesced 192-dot
// (float4 g_partial quarters + coalesced w1 row), shuffle reduce.
// High MLP -> latency hidden (vs 15-25us for the single-block version).
// ---------------------------------------------------------------------------
__global__ void __launch_bounds__(256)
compute_t_kernel(const float* __restrict__ w1,
                 const float* __restrict__ gamma,
                 const float* __restrict__ beta,
                 const float* __restrict__ rmean,
                 const float* __restrict__ rvar) {
    int wid  = blockIdx.x * 8 + (threadIdx.x >> 5);   // [0, 192)
    int lane = threadIdx.x & 31;
    int b = wid / RR;
    int r = wid % RR;

    const float* wr = w1 + r * DIMC;
    const float4* gp = reinterpret_cast<const float4*>(g_partial) + b * DIMC;

    float acc = 0.f;
    #pragma unroll
    for (int i = 0; i < DIMC / 32; ++i) {
        int k = lane + 32 * i;
        float4 q = gp[k];                      // 4 quarter-sums for (b,k)
        float mean = ((q.x + q.y) + (q.z + q.w)) * (1.f / (float)PLANE);
        acc = fmaf(mean, wr[k], acc);
    }
    #pragma unroll
    for (int o = 16; o > 0; o >>= 1) acc += __shfl_down_sync(0xffffffffu, acc, o);
    if (lane == 0) {
        acc = gamma[r] * (acc - rmean[r]) * rsqrtf(rvar[r] + EPS_BN) + beta[r];
        g_t[wid] = fmaxf(acc, 0.f);
    }
}

// ---------------------------------------------------------------------------
// Kernel 3: fused taps + masked depthwise conv. BYTE-IDENTICAL to R12
// (measured 65.4us). Grid = 768 planes x 8 chunks = 6144 blocks. Prologue:
// warps 0..3 compute this plane's 4 surviving taps from g_t + 4 w2 rows.
// out[y][x] = w0*X[y-1][x-1] + w1*X[y-1][x] + w2*X[y-1][x+1] + w3*X[y][x-1]+b
// ---------------------------------------------------------------------------
__global__ void __launch_bounds__(256, 8)
conv_kernel(const float* __restrict__ x,
            const float* __restrict__ w2,
            const float* __restrict__ b2,
            const float* __restrict__ bias,
            float* __restrict__ out) {
    int plane = blockIdx.x >> 3;       // forward order (proven access pattern)
    int chunk = blockIdx.x & 7;
    int b = plane / DIMC;
    int c = plane % DIMC;
    int lane = threadIdx.x & 31;
    int warp = threadIdx.x >> 5;

    __shared__ float sw[4];
    if (warp < 4) {
        int row = c * 9 + warp;                    // surviving mask-A taps 0..3
        const float* wr = w2 + (size_t)row * RR;
        const float* tb = g_t + b * RR;
        float acc = tb[lane] * wr[lane];
        if (lane < 16) acc = fmaf(tb[lane + 32], wr[lane + 32], acc);
        #pragma unroll
        for (int o = 16; o > 0; o >>= 1)
            acc += __shfl_down_sync(0xffffffffu, acc, o);
        if (lane == 0) sw[warp] = acc + b2[row];
    }
    __syncthreads();

    const float w0 = sw[0], w1v = sw[1], w2v = sw[2], w3 = sw[3];
    const float bv = __ldg(&bias[c]);

    int ty = threadIdx.x >> 6;         // 0..3
    int tx = threadIdx.x & 63;
    int x0 = tx << 2;
    const float* Xp = x   + (size_t)plane * PLANE;
    float*       Op = out + (size_t)plane * PLANE;

    #pragma unroll 2
    for (int rg = 0; rg < 8; ++rg) {
        int y = chunk * 32 + rg * 4 + ty;
        const float* cur = Xp + y * WW;

        float4 c4 = *reinterpret_cast<const float4*>(cur + x0);
        float cl  = (x0 > 0) ? cur[x0 - 1] : 0.f;

        float4 a4 = make_float4(0.f, 0.f, 0.f, 0.f);
        float al = 0.f, ar = 0.f;
        if (y > 0) {
            const float* ab = cur - WW;
            a4 = *reinterpret_cast<const float4*>(ab + x0);
            al = (x0 > 0)      ? ab[x0 - 1] : 0.f;
            ar = (x0 < WW - 4) ? ab[x0 + 4] : 0.f;
        }

        float4 o;
        o.x = fmaf(w0, al,   fmaf(w1v, a4.x, fmaf(w2v, a4.y, fmaf(w3, cl,   bv))));
        o.y = fmaf(w0, a4.x, fmaf(w1v, a4.y, fmaf(w2v, a4.z, fmaf(w3, c4.x, bv))));
        o.z = fmaf(w0, a4.y, fmaf(w1v, a4.z, fmaf(w2v, a4.w, fmaf(w3, c4.y, bv))));
        o.w = fmaf(w0, a4.z, fmaf(w1v, a4.w, fmaf(w2v, ar,   fmaf(w3, c4.z, bv))));

        *reinterpret_cast<float4*>(Op + y * WW + x0) = o;
    }
}

// ---------------------------------------------------------------------------
extern "C" void kernel_launch(void* const* d_in, const int* in_sizes, int n_in,
                              void* d_out, int out_size) {
    const float* x     = (const float*)d_in[0];
    const float* w1    = (const float*)d_in[1];
    const float* gamma = (const float*)d_in[2];
    const float* beta  = (const float*)d_in[3];
    const float* rmean = (const float*)d_in[4];
    const float* rvar  = (const float*)d_in[5];
    const float* w2    = (const float*)d_in[6];
    const float* b2    = (const float*)d_in[7];
    const float* bias  = (const float*)d_in[8];
    float* out = (float*)d_out;

    pool_partial_kernel<<<NPLANES * 4, 256>>>(x);
    compute_t_kernel<<<24, 256>>>(w1, gamma, beta, rmean, rvar);
    conv_kernel<<<NPLANES * 8, 256>>>(x, w2, b2, bias, out);
}